// round 1
// baseline (speedup 1.0000x reference)
#include <cuda_runtime.h>
#include <math.h>

// out[row] = tanh(sqrt(sum_j (w[row][j] - x[j])^2)), row in [0, 1048576), j in [0, 256)
// Warp-per-row: lane l handles columns [4l,4l+4) and [128+4l, 128+4l+4) via float4.

__global__ __launch_bounds__(256) void sonia_l2_tanh_kernel(
    const float* __restrict__ x,
    const float* __restrict__ w,
    float* __restrict__ out,
    int n_rows)
{
    const int warp_id = (blockIdx.x * blockDim.x + threadIdx.x) >> 5;
    const int lane    = threadIdx.x & 31;
    if (warp_id >= n_rows) return;

    const float4* __restrict__ wr = reinterpret_cast<const float4*>(w) + (size_t)warp_id * 64;
    const float4* __restrict__ xr = reinterpret_cast<const float4*>(x);

    // Two fully-coalesced 512B warp loads per row
    float4 w0 = wr[lane];
    float4 w1 = wr[lane + 32];
    float4 x0 = xr[lane];
    float4 x1 = xr[lane + 32];

    float d, s = 0.0f;
    d = w0.x - x0.x; s = fmaf(d, d, s);
    d = w0.y - x0.y; s = fmaf(d, d, s);
    d = w0.z - x0.z; s = fmaf(d, d, s);
    d = w0.w - x0.w; s = fmaf(d, d, s);
    d = w1.x - x1.x; s = fmaf(d, d, s);
    d = w1.y - x1.y; s = fmaf(d, d, s);
    d = w1.z - x1.z; s = fmaf(d, d, s);
    d = w1.w - x1.w; s = fmaf(d, d, s);

    // Butterfly reduce across the warp
    #pragma unroll
    for (int off = 16; off > 0; off >>= 1)
        s += __shfl_xor_sync(0xFFFFFFFFu, s, off);

    if (lane == 0)
        out[warp_id] = tanhf(sqrtf(s));
}

extern "C" void kernel_launch(void* const* d_in, const int* in_sizes, int n_in,
                              void* d_out, int out_size)
{
    const float* x = (const float*)d_in[0];   // input  [1, 256]
    const float* w = (const float*)d_in[1];   // weight [out_size, 256]
    float* out     = (float*)d_out;

    const int n_rows = out_size;              // 1048576
    const int warps_per_block = 256 / 32;     // 8
    const int blocks = (n_rows + warps_per_block - 1) / warps_per_block;

    sonia_l2_tanh_kernel<<<blocks, 256>>>(x, w, out, n_rows);
}

// round 2
// speedup vs baseline: 1.0380x; 1.0380x over previous
#include <cuda_runtime.h>
#include <math.h>

// out[row] = tanh(sqrt(sum_j (w[row][j] - x[j])^2)), row in [0, 1048576), j in [0, 256)
// Warp handles TWO rows: 4 independent front-batched 128-bit streaming loads
// (512B fully-coalesced each) -> deeper DRAM MLP per warp.

__global__ __launch_bounds__(256) void sonia_l2_tanh_kernel2(
    const float* __restrict__ x,
    const float* __restrict__ w,
    float* __restrict__ out,
    int n_rows)
{
    const int warp_id = (blockIdx.x * blockDim.x + threadIdx.x) >> 5;
    const int lane    = threadIdx.x & 31;
    const int row0    = warp_id * 2;
    if (row0 >= n_rows) return;

    const float4* __restrict__ wr = reinterpret_cast<const float4*>(w) + (size_t)row0 * 64;
    const float4* __restrict__ xr = reinterpret_cast<const float4*>(x);

    // x is tiny and re-read by every warp: L1/L2 resident.
    const float4 x0 = __ldg(xr + lane);
    const float4 x1 = __ldg(xr + lane + 32);

    // 4 independent streaming loads (evict-first: pure pass-through data).
    const float4 a0 = __ldcs(wr + lane);
    const float4 a1 = __ldcs(wr + lane + 32);
    const float4 b0 = __ldcs(wr + lane + 64);
    const float4 b1 = __ldcs(wr + lane + 96);

    float d;
    float sa = 0.0f, sb = 0.0f;
    d = a0.x - x0.x; sa = fmaf(d, d, sa);
    d = a0.y - x0.y; sa = fmaf(d, d, sa);
    d = a0.z - x0.z; sa = fmaf(d, d, sa);
    d = a0.w - x0.w; sa = fmaf(d, d, sa);
    d = a1.x - x1.x; sa = fmaf(d, d, sa);
    d = a1.y - x1.y; sa = fmaf(d, d, sa);
    d = a1.z - x1.z; sa = fmaf(d, d, sa);
    d = a1.w - x1.w; sa = fmaf(d, d, sa);

    d = b0.x - x0.x; sb = fmaf(d, d, sb);
    d = b0.y - x0.y; sb = fmaf(d, d, sb);
    d = b0.z - x0.z; sb = fmaf(d, d, sb);
    d = b0.w - x0.w; sb = fmaf(d, d, sb);
    d = b1.x - x1.x; sb = fmaf(d, d, sb);
    d = b1.y - x1.y; sb = fmaf(d, d, sb);
    d = b1.z - x1.z; sb = fmaf(d, d, sb);
    d = b1.w - x1.w; sb = fmaf(d, d, sb);

    // Butterfly reduce both sums across the warp.
    #pragma unroll
    for (int off = 16; off > 0; off >>= 1) {
        sa += __shfl_xor_sync(0xFFFFFFFFu, sa, off);
        sb += __shfl_xor_sync(0xFFFFFFFFu, sb, off);
    }

    if (lane == 0) {
        out[row0]     = tanhf(sqrtf(sa));
        if (row0 + 1 < n_rows)
            out[row0 + 1] = tanhf(sqrtf(sb));
    }
}

extern "C" void kernel_launch(void* const* d_in, const int* in_sizes, int n_in,
                              void* d_out, int out_size)
{
    const float* x = (const float*)d_in[0];   // input  [1, 256]
    const float* w = (const float*)d_in[1];   // weight [out_size, 256]
    float* out     = (float*)d_out;

    const int n_rows = out_size;              // 1048576
    // 8 warps/block, 2 rows/warp -> 16 rows per block
    const int rows_per_block = 16;
    const int blocks = (n_rows + rows_per_block - 1) / rows_per_block;

    sonia_l2_tanh_kernel2<<<blocks, 256>>>(x, w, out, n_rows);
}